// round 1
// baseline (speedup 1.0000x reference)
#include <cuda_runtime.h>
#include <math.h>

#define N_NODES 50000
#define D_IN 128
#define D_HID 256
#define MAX_SRC 8192

// persistent device scratch (no allocations allowed)
__device__ int g_deg[N_NODES];
__device__ int g_srcs[MAX_SRC];
__device__ int g_nsrc;
__device__ int g_agent;
__device__ int g_is64;

// ---------------------------------------------------------------------------
// K0: zero the degree histogram; block 0 detects edge dtype + decodes agent_i
// ---------------------------------------------------------------------------
__global__ void k_init(const void* __restrict__ edges, const void* __restrict__ agent_ptr) {
    int i = blockIdx.x * blockDim.x + threadIdx.x;
    if (i < N_NODES) g_deg[i] = 0;
    if (blockIdx.x == 0 && threadIdx.x == 0) {
        g_nsrc = 0;
        // dtype detection: for int64 little-endian values < 50000, every odd
        // 32-bit word is zero. For int32 random values in [0,50000) the odds
        // of 16 consecutive odd words being zero are ~0.
        const int* w = (const int*)edges;
        int is64 = 1;
        #pragma unroll
        for (int j = 0; j < 16; j++) {
            if (w[2 * j + 1] != 0) { is64 = 0; break; }
        }
        g_is64 = is64;
        // agent_i decode: works for int32 and int64 (LE); fall back to float
        int a = *(const int*)agent_ptr;
        if (a < 0 || a >= N_NODES) {
            float f = *(const float*)agent_ptr;
            a = (int)f;
        }
        g_agent = a;
    }
}

// ---------------------------------------------------------------------------
// K1: one pass over dst: full degree histogram + collect srcs of edges->agent
// ---------------------------------------------------------------------------
__global__ void k_hist(const void* __restrict__ edges, long long E) {
    long long i = (long long)blockIdx.x * blockDim.x + threadIdx.x;
    if (i >= E) return;
    const int agent = g_agent;
    int d;
    if (g_is64) {
        const long long* p = (const long long*)edges;
        d = (int)p[E + i];
        atomicAdd(&g_deg[d], 1);
        if (d == agent) {
            int s = (int)p[i];
            int pos = atomicAdd(&g_nsrc, 1);
            if (pos < MAX_SRC) g_srcs[pos] = s;
        }
    } else {
        const int* p = (const int*)edges;
        d = p[E + i];
        atomicAdd(&g_deg[d], 1);
        if (d == agent) {
            int s = p[i];
            int pos = atomicAdd(&g_nsrc, 1);
            if (pos < MAX_SRC) g_srcs[pos] = s;
        }
    }
}

// ---------------------------------------------------------------------------
// K2: single block. Aggregate weighted state rows (linear GCN trick),
//     GEMV through conv_w, then the full MLP head.
// ---------------------------------------------------------------------------
__global__ void __launch_bounds__(256, 1) k_mlp(
    const float* __restrict__ state,
    const float* __restrict__ conv_w, const float* __restrict__ conv_b,
    const float* __restrict__ fc1_w,  const float* __restrict__ fc1_b,
    const float* __restrict__ ln1_w,  const float* __restrict__ ln1_b,
    const float* __restrict__ fc2_w,  const float* __restrict__ fc2_b,
    const float* __restrict__ ln2_w,  const float* __restrict__ ln2_b,
    const float* __restrict__ mu_w,   const float* __restrict__ mu_b,
    float* __restrict__ out)
{
    __shared__ float agg[D_IN];     // aggregated (norm-weighted) input row
    __shared__ float xv[D_HID];     // activation vector between layers
    __shared__ float red1[256];
    __shared__ float red2[256];

    const int t = threadIdx.x;
    const int agent = g_agent;
    const float dinv_a = rsqrtf((float)(g_deg[agent] + 1));
    const int n = min(g_nsrc, MAX_SRC);

    // ---- aggregate: agg[k] = dinv_a^2 * state[agent][k] + sum_e norm_e * state[src_e][k]
    if (t < D_IN) {
        float acc = dinv_a * dinv_a * state[(long long)agent * D_IN + t];
        for (int m = 0; m < n; m++) {
            int s = g_srcs[m];
            float norm = rsqrtf((float)(g_deg[s] + 1)) * dinv_a;
            acc += norm * state[(long long)s * D_IN + t];
        }
        agg[t] = acc;
    }
    __syncthreads();

    // ---- GCN linear: x[t] = relu( agg @ conv_w[:,t] + conv_b[t] )
    {
        float acc = conv_b[t];
        #pragma unroll 8
        for (int k = 0; k < D_IN; k++) acc += agg[k] * conv_w[k * D_HID + t];
        xv[t] = fmaxf(acc, 0.0f);
    }
    __syncthreads();

    // ---- fc1 + LN + relu
    {
        float acc = fc1_b[t];
        #pragma unroll 8
        for (int k = 0; k < D_HID; k++) acc += xv[k] * fc1_w[k * 256 + t];
        // block reduce sum & sumsq
        red1[t] = acc; red2[t] = acc * acc;
        __syncthreads();
        #pragma unroll
        for (int off = 128; off > 0; off >>= 1) {
            if (t < off) { red1[t] += red1[t + off]; red2[t] += red2[t + off]; }
            __syncthreads();
        }
        float mean = red1[0] * (1.0f / 256.0f);
        float var  = red2[0] * (1.0f / 256.0f) - mean * mean;
        float y = (acc - mean) * rsqrtf(var + 1e-5f) * ln1_w[t] + ln1_b[t];
        __syncthreads();            // everyone done reading xv / red
        xv[t] = fmaxf(y, 0.0f);
    }
    __syncthreads();

    // ---- fc2 + LN + relu
    {
        float acc = fc2_b[t];
        #pragma unroll 8
        for (int k = 0; k < 256; k++) acc += xv[k] * fc2_w[k * 256 + t];
        red1[t] = acc; red2[t] = acc * acc;
        __syncthreads();
        #pragma unroll
        for (int off = 128; off > 0; off >>= 1) {
            if (t < off) { red1[t] += red1[t + off]; red2[t] += red2[t + off]; }
            __syncthreads();
        }
        float mean = red1[0] * (1.0f / 256.0f);
        float var  = red2[0] * (1.0f / 256.0f) - mean * mean;
        float y = (acc - mean) * rsqrtf(var + 1e-5f) * ln2_w[t] + ln2_b[t];
        __syncthreads();
        xv[t] = fmaxf(y, 0.0f);
    }
    __syncthreads();

    // ---- mu head + sigmoid: 8 outputs, one warp each (warp-reduced dot)
    if (t < 256) {
        int w = t >> 5;             // warp id 0..7 -> output index
        int lane = t & 31;
        float acc = 0.0f;
        #pragma unroll
        for (int k = lane; k < 256; k += 32) acc += xv[k] * mu_w[k * 8 + w];
        #pragma unroll
        for (int off = 16; off > 0; off >>= 1)
            acc += __shfl_down_sync(0xffffffffu, acc, off);
        if (lane == 0) {
            float z = acc + mu_b[w];
            out[w] = 1.0f / (1.0f + expf(-z));
        }
    }
}

// ---------------------------------------------------------------------------
extern "C" void kernel_launch(void* const* d_in, const int* in_sizes, int n_in,
                              void* d_out, int out_size) {
    const float* state  = (const float*)d_in[0];
    const void*  edges  = d_in[1];
    const void*  agent  = d_in[2];
    const float* conv_w = (const float*)d_in[3];
    const float* conv_b = (const float*)d_in[4];
    const float* fc1_w  = (const float*)d_in[5];
    const float* fc1_b  = (const float*)d_in[6];
    const float* ln1_w  = (const float*)d_in[7];
    const float* ln1_b  = (const float*)d_in[8];
    const float* fc2_w  = (const float*)d_in[9];
    const float* fc2_b  = (const float*)d_in[10];
    const float* ln2_w  = (const float*)d_in[11];
    const float* ln2_b  = (const float*)d_in[12];
    const float* mu_w   = (const float*)d_in[13];
    const float* mu_b   = (const float*)d_in[14];

    long long E = (long long)in_sizes[1] / 2;

    k_init<<<(N_NODES + 255) / 256, 256>>>(edges, agent);
    k_hist<<<(unsigned)((E + 255) / 256), 256>>>(edges, E);
    k_mlp<<<1, 256>>>(state, conv_w, conv_b, fc1_w, fc1_b, ln1_w, ln1_b,
                      fc2_w, fc2_b, ln2_w, ln2_b, mu_w, mu_b, (float*)d_out);
}

// round 2
// speedup vs baseline: 1.0609x; 1.0609x over previous
#include <cuda_runtime.h>
#include <math.h>

#define N_NODES 50000
#define D_IN 128
#define D_HID 256
#define MAX_SRC 8192
#define SH_SRC  4096

// persistent device scratch (no allocations allowed)
__device__ int g_deg[N_NODES];
__device__ int g_srcs[MAX_SRC];
__device__ int g_nsrc;
__device__ int g_agent;
__device__ int g_is64;

// ---------------------------------------------------------------------------
// K0: zero the degree histogram (int4 stores); thread 0 of block 0 decodes
//     edge dtype + agent index.
// ---------------------------------------------------------------------------
__global__ void k_init(const void* __restrict__ edges, const void* __restrict__ agent_ptr) {
    int i = blockIdx.x * blockDim.x + threadIdx.x;      // int4 index
    int4 z = make_int4(0, 0, 0, 0);
    int base = i * 4;
    if (base + 3 < N_NODES) {
        *reinterpret_cast<int4*>(&g_deg[base]) = z;
    } else if (base < N_NODES) {
        for (int j = base; j < N_NODES; j++) g_deg[j] = 0;
    }
    if (i == 0) {
        g_nsrc = 0;
        // int64 detection: odd 32-bit words of small int64 values are zero.
        const int* w = (const int*)edges;
        int is64 = 1;
        #pragma unroll
        for (int j = 0; j < 16; j++) {
            if (w[2 * j + 1] != 0) { is64 = 0; break; }
        }
        g_is64 = is64;
        int a = *(const int*)agent_ptr;
        if (a < 0 || a >= N_NODES) a = (int)(*(const float*)agent_ptr);
        g_agent = a;
    }
}

// ---------------------------------------------------------------------------
// K1: one pass over dst (2 edges/thread, 16B loads): degree histogram +
//     collect srcs of edges whose dst == agent.
// ---------------------------------------------------------------------------
__global__ void k_hist(const void* __restrict__ edges, long long E) {
    long long i = 2LL * ((long long)blockIdx.x * blockDim.x + threadIdx.x);
    if (i >= E) return;
    const int agent = g_agent;
    int d0, d1 = -1;
    if (g_is64) {
        const longlong2* p2 = (const longlong2*)((const long long*)edges + E + i);
        longlong2 v = *p2;
        d0 = (int)v.x;
        if (i + 1 < E) d1 = (int)v.y;
    } else {
        const int2* p2 = (const int2*)((const int*)edges + E + i);
        int2 v = *p2;
        d0 = v.x;
        if (i + 1 < E) d1 = v.y;
    }
    atomicAdd(&g_deg[d0], 1);
    if (d1 >= 0) atomicAdd(&g_deg[d1], 1);
    if (d0 == agent || d1 == agent) {
        // rare path: fetch matching srcs
        if (d0 == agent) {
            int s = g_is64 ? (int)((const long long*)edges)[i] : ((const int*)edges)[i];
            int pos = atomicAdd(&g_nsrc, 1);
            if (pos < MAX_SRC) g_srcs[pos] = s;
        }
        if (d1 == agent) {
            int s = g_is64 ? (int)((const long long*)edges)[i + 1] : ((const int*)edges)[i + 1];
            int pos = atomicAdd(&g_nsrc, 1);
            if (pos < MAX_SRC) g_srcs[pos] = s;
        }
    }
}

// ---------------------------------------------------------------------------
// warp+block reduction helpers (256 threads, 8 warps)
// ---------------------------------------------------------------------------
__device__ __forceinline__ void block_mean_var(float v, int t, float* sh,
                                               float& mean, float& var) {
    float s = v, q = v * v;
    #pragma unroll
    for (int off = 16; off > 0; off >>= 1) {
        s += __shfl_down_sync(0xffffffffu, s, off);
        q += __shfl_down_sync(0xffffffffu, q, off);
    }
    int w = t >> 5, lane = t & 31;
    if (lane == 0) { sh[w] = s; sh[8 + w] = q; }
    __syncthreads();
    if (t < 32) {
        float s2 = (t < 8) ? sh[t] : 0.0f;
        float q2 = (t < 8) ? sh[8 + t] : 0.0f;
        #pragma unroll
        for (int off = 4; off > 0; off >>= 1) {
            s2 += __shfl_down_sync(0xffffffffu, s2, off);
            q2 += __shfl_down_sync(0xffffffffu, q2, off);
        }
        if (t == 0) { sh[16] = s2; sh[17] = q2; }
    }
    __syncthreads();
    mean = sh[16] * (1.0f / 256.0f);
    var  = sh[17] * (1.0f / 256.0f) - mean * mean;
}

// ---------------------------------------------------------------------------
// K2: single block, 256 threads. Weighted aggregation (GCN linearity trick),
//     conv GEMV, fc1+LN+relu, fc2+LN+relu, mu+sigmoid.
// ---------------------------------------------------------------------------
__global__ void __launch_bounds__(256, 1) k_mlp(
    const float* __restrict__ state,
    const float* __restrict__ conv_w, const float* __restrict__ conv_b,
    const float* __restrict__ fc1_w,  const float* __restrict__ fc1_b,
    const float* __restrict__ ln1_w,  const float* __restrict__ ln1_b,
    const float* __restrict__ fc2_w,  const float* __restrict__ fc2_b,
    const float* __restrict__ ln2_w,  const float* __restrict__ ln2_b,
    const float* __restrict__ mu_w,   const float* __restrict__ mu_b,
    float* __restrict__ out)
{
    __shared__ int   ssrc[SH_SRC];
    __shared__ float snorm[SH_SRC];
    __shared__ float agg[D_IN];
    __shared__ float xv[D_HID];
    __shared__ float red[256];
    __shared__ float sh[32];

    const int t = threadIdx.x;
    const int agent = g_agent;
    const float dinv_a = rsqrtf((float)(g_deg[agent] + 1));
    const int n = min(g_nsrc, SH_SRC);

    // prefetch srcs + norms (parallel over sources)
    for (int m = t; m < n; m += 256) {
        int s = g_srcs[m];
        ssrc[m]  = s;
        snorm[m] = rsqrtf((float)(g_deg[s] + 1)) * dinv_a;
    }
    __syncthreads();

    // ---- aggregation: 2 chains x 128 dims, unrolled for MLP
    {
        const int d = t & 127;
        const int h = t >> 7;
        float acc = 0.0f;
        #pragma unroll 4
        for (int m = h; m < n; m += 2)
            acc += snorm[m] * __ldg(&state[(long long)ssrc[m] * D_IN + d]);
        red[t] = acc;
        __syncthreads();
        if (t < D_IN) {
            float self = dinv_a * dinv_a * state[(long long)agent * D_IN + t];
            agg[t] = red[t] + red[t + 128] + self;
        }
        __syncthreads();
    }

    // ---- GCN linear + relu: xv[t] = relu(agg @ conv_w[:,t] + conv_b[t])
    {
        float acc = conv_b[t];
        #pragma unroll 8
        for (int k = 0; k < D_IN; k++) acc += agg[k] * __ldg(&conv_w[k * D_HID + t]);
        xv[t] = fmaxf(acc, 0.0f);
    }
    __syncthreads();

    // ---- fc1 + LN + relu
    {
        float acc = fc1_b[t];
        #pragma unroll 8
        for (int k = 0; k < D_HID; k++) acc += xv[k] * __ldg(&fc1_w[k * 256 + t]);
        float mean, var;
        block_mean_var(acc, t, sh, mean, var);
        float y = (acc - mean) * rsqrtf(var + 1e-5f) * ln1_w[t] + ln1_b[t];
        __syncthreads();
        xv[t] = fmaxf(y, 0.0f);
        __syncthreads();
    }

    // ---- fc2 + LN + relu
    {
        float acc = fc2_b[t];
        #pragma unroll 8
        for (int k = 0; k < 256; k++) acc += xv[k] * __ldg(&fc2_w[k * 256 + t]);
        float mean, var;
        block_mean_var(acc, t, sh, mean, var);
        float y = (acc - mean) * rsqrtf(var + 1e-5f) * ln2_w[t] + ln2_b[t];
        __syncthreads();
        xv[t] = fmaxf(y, 0.0f);
        __syncthreads();
    }

    // ---- mu head + sigmoid: 8 outputs, one warp each
    {
        int w = t >> 5, lane = t & 31;
        float acc = 0.0f;
        #pragma unroll
        for (int k = lane; k < 256; k += 32) acc += xv[k] * __ldg(&mu_w[k * 8 + w]);
        #pragma unroll
        for (int off = 16; off > 0; off >>= 1)
            acc += __shfl_down_sync(0xffffffffu, acc, off);
        if (lane == 0) {
            float z = acc + mu_b[w];
            out[w] = 1.0f / (1.0f + expf(-z));
        }
    }
}

// ---------------------------------------------------------------------------
extern "C" void kernel_launch(void* const* d_in, const int* in_sizes, int n_in,
                              void* d_out, int out_size) {
    const float* state  = (const float*)d_in[0];
    const void*  edges  = d_in[1];
    const void*  agent  = d_in[2];
    const float* conv_w = (const float*)d_in[3];
    const float* conv_b = (const float*)d_in[4];
    const float* fc1_w  = (const float*)d_in[5];
    const float* fc1_b  = (const float*)d_in[6];
    const float* ln1_w  = (const float*)d_in[7];
    const float* ln1_b  = (const float*)d_in[8];
    const float* fc2_w  = (const float*)d_in[9];
    const float* fc2_b  = (const float*)d_in[10];
    const float* ln2_w  = (const float*)d_in[11];
    const float* ln2_b  = (const float*)d_in[12];
    const float* mu_w   = (const float*)d_in[13];
    const float* mu_b   = (const float*)d_in[14];

    long long E = (long long)in_sizes[1] / 2;

    int zthreads = (N_NODES + 3) / 4;                     // int4 per thread
    k_init<<<(zthreads + 255) / 256, 256>>>(edges, agent);
    long long pairs = (E + 1) / 2;
    k_hist<<<(unsigned)((pairs + 255) / 256), 256>>>(edges, E);
    k_mlp<<<1, 256>>>(state, conv_w, conv_b, fc1_w, fc1_b, ln1_w, ln1_b,
                      fc2_w, fc2_b, ln2_w, ln2_b, mu_w, mu_b, (float*)d_out);
}